// round 17
// baseline (speedup 1.0000x reference)
#include <cuda_runtime.h>
#include <math.h>
#include <stdint.h>

#define Bq    4096
#define Nn    10
#define BN    40960
#define DIN   32
#define Dd    128
#define PHId  256
#define RHOd  128
#define Ll    3
#define EPS   1e-5f
#define KAUG  384

// ---------------- scratch ----------------
__device__ float gH  [BN * Dd];
__device__ float gXa [BN * KAUG];
__device__ float gAgg[BN * Dd];
__device__ float gP1 [BN * PHId];
__device__ float gP2 [BN * PHId];
__device__ float gS  [2 * Bq * PHId];
__device__ float gR  [2 * Bq * RHOd];
__device__ float gMix[Bq * 300];
__device__ float gRowA[BN];

#define ASZ  (128 * 20)
#define BSZ  (16 * 136)
#define YLD  132

__device__ __forceinline__ void cpa16(uint32_t d, const void* s) {
    asm volatile("cp.async.ca.shared.global [%0],[%1],16;\n" :: "r"(d), "l"(s));
}
__device__ __forceinline__ void cp_commit() { asm volatile("cp.async.commit_group;\n"); }

__device__ __forceinline__ void mma_tf32(float c[4], uint32_t a0, uint32_t a1, uint32_t a2, uint32_t a3,
                                         uint32_t b0, uint32_t b1) {
    asm("mma.sync.aligned.m16n8k8.row.col.f32.tf32.tf32.f32 "
        "{%0,%1,%2,%3},{%4,%5,%6,%7},{%8,%9},{%0,%1,%2,%3};"
        : "+f"(c[0]), "+f"(c[1]), "+f"(c[2]), "+f"(c[3])
        : "r"(a0), "r"(a1), "r"(a2), "r"(a3), "r"(b0), "r"(b1));
}

template<int K, bool STAGE_A>
__device__ __forceinline__ void issue_stage(const float* __restrict__ Ag, const float* __restrict__ Bg,
                                            int ldb, size_t Rb, int cb, int ch,
                                            float* Asb, float* Bsb, int tid)
{
    if (STAGE_A) {
        const int r = tid >> 1, koff = (tid & 1) * 8;
        const float* src = Ag + (Rb + r) * K + ch * 16 + koff;
        uint32_t d = (uint32_t)__cvta_generic_to_shared(Asb + r * 20 + koff);
        cpa16(d, src); cpa16(d + 16, src + 4);
    }
    {
        const int k = tid >> 4, c = (tid & 15) * 8;
        const float* src = Bg + (size_t)(ch * 16 + k) * ldb + cb + c;
        uint32_t d = (uint32_t)__cvta_generic_to_shared(Bsb + k * 136 + c);
        cpa16(d, src); cpa16(d + 16, src + 4);
    }
    cp_commit();
}

// A stride KAUG; B rows 0-255 from Wab (W0|W1 stacked), rows 256-383 from Wr
__device__ __forceinline__ void issue_stage_ln(const float* __restrict__ Ag,
                                               const float* __restrict__ Wab,
                                               const float* __restrict__ Wr,
                                               size_t Rb, int ch, float* Asb, float* Bsb, int tid)
{
    {
        const int r = tid >> 1, koff = (tid & 1) * 8;
        const float* src = Ag + (Rb + r) * KAUG + ch * 16 + koff;
        uint32_t d = (uint32_t)__cvta_generic_to_shared(Asb + r * 20 + koff);
        cpa16(d, src); cpa16(d + 16, src + 4);
    }
    {
        const int k = tid >> 4, c = (tid & 15) * 8;
        const int gr = ch * 16 + k;
        const float* src = (gr < 256) ? (Wab + (size_t)gr * Dd + c)
                                      : (Wr + (size_t)(gr - 256) * Dd + c);
        uint32_t d = (uint32_t)__cvta_generic_to_shared(Bsb + k * 136 + c);
        cpa16(d, src); cpa16(d + 16, src + 4);
    }
    cp_commit();
}

__device__ __forceinline__ void compute_chunk(const float* __restrict__ Asb, int lda, int koff0,
                                              const float* __restrict__ Bsb,
                                              int wr, int wc, int g, int tg, float C[2][8][4])
{
    #pragma unroll
    for (int kt = 0; kt < 2; ++kt) {
        uint32_t a[2][4];
        #pragma unroll
        for (int mt = 0; mt < 2; ++mt) {
            const int r0 = wr + mt * 16;
            a[mt][0] = __float_as_uint(Asb[(r0 + g    ) * lda + koff0 + kt * 8 + tg    ]);
            a[mt][1] = __float_as_uint(Asb[(r0 + g + 8) * lda + koff0 + kt * 8 + tg    ]);
            a[mt][2] = __float_as_uint(Asb[(r0 + g    ) * lda + koff0 + kt * 8 + tg + 4]);
            a[mt][3] = __float_as_uint(Asb[(r0 + g + 8) * lda + koff0 + kt * 8 + tg + 4]);
        }
        #pragma unroll
        for (int nt = 0; nt < 8; ++nt) {
            uint32_t b0 = __float_as_uint(Bsb[(kt * 8 + tg    ) * 136 + wc + nt * 8 + g]);
            uint32_t b1 = __float_as_uint(Bsb[(kt * 8 + tg + 4) * 136 + wc + nt * 8 + g]);
            mma_tf32(C[0][nt], a[0][0], a[0][1], a[0][2], a[0][3], b0, b1);
            mma_tf32(C[1][nt], a[1][0], a[1][1], a[1][2], a[1][3], b0, b1);
        }
    }
}

template<int K, int LDB_, bool STAGE_A>
__device__ __forceinline__ void gemm_db(const float* __restrict__ Ag, const float* __restrict__ Bg,
                                        size_t Rb, int cb,
                                        float* As2, float* Bs2, const float* Yb,
                                        int wr, int wc, int g, int tg, int tid, float C[2][8][4])
{
    constexpr int CH = K / 16;
    issue_stage<K, STAGE_A>(Ag, Bg, LDB_, Rb, cb, 0, As2, Bs2, tid);
    issue_stage<K, STAGE_A>(Ag, Bg, LDB_, Rb, cb, 1 < CH ? 1 : 0, As2 + ASZ, Bs2 + BSZ, tid);
    #pragma unroll 1
    for (int ch = 0; ch < CH; ++ch) {
        if (ch + 1 < CH) asm volatile("cp.async.wait_group 1;\n");
        else             asm volatile("cp.async.wait_group 0;\n");
        __syncthreads();
        const int s = ch & 1;
        if (STAGE_A) compute_chunk(As2 + s * ASZ, 20, 0,       Bs2 + s * BSZ, wr, wc, g, tg, C);
        else         compute_chunk(Yb,           YLD, ch * 16, Bs2 + s * BSZ, wr, wc, g, tg, C);
        __syncthreads();
        if (ch + 2 < CH)
            issue_stage<K, STAGE_A>(Ag, Bg, LDB_, Rb, cb, ch + 2, As2 + s * ASZ, Bs2 + s * BSZ, tid);
    }
}

#define GEMM_IDS \
    const int tid  = threadIdx.x; \
    const int warp = tid >> 5, lane = tid & 31; \
    const int g    = lane >> 2, tg = lane & 3; \
    const int wr   = (warp >> 1) * 32; \
    const int wc   = (warp & 1) * 64; \
    float C[2][8][4]; \
    _Pragma("unroll") for (int _a = 0; _a < 2; ++_a) \
    _Pragma("unroll") for (int _b = 0; _b < 8; ++_b) \
    _Pragma("unroll") for (int _c = 0; _c < 4; ++_c) C[_a][_b][_c] = 0.f;

// ---------------- plain GEMM (phi1/phi2/rho) ----------------
template<int K, int NTOT, bool RELU, bool HASBIAS>
__global__ __launch_bounds__(256)
void gemm_tc(const float* __restrict__ Ag, const float* __restrict__ Bg,
             const float* __restrict__ bias, float* __restrict__ Cg)
{
    __shared__ float As2[2 * ASZ];
    __shared__ float Bs2[2 * BSZ];
    GEMM_IDS
    const size_t Rb = (size_t)blockIdx.x * 128;
    const int cb = blockIdx.y * 128;

    gemm_db<K, NTOT, true>(Ag, Bg, Rb, cb, As2, Bs2, nullptr, wr, wc, g, tg, tid, C);

    #pragma unroll
    for (int mt = 0; mt < 2; ++mt) {
        const size_t row0 = Rb + wr + mt * 16 + g;
        #pragma unroll
        for (int nt = 0; nt < 8; ++nt) {
            const int col = cb + wc + nt * 8 + 2 * tg;
            float bx = 0.f, by = 0.f;
            if (HASBIAS) { float2 bb = *(const float2*)&bias[col]; bx = bb.x; by = bb.y; }
            float v0 = C[mt][nt][0] + bx, v1 = C[mt][nt][1] + by;
            float v2 = C[mt][nt][2] + bx, v3 = C[mt][nt][3] + by;
            if (RELU) { v0 = fmaxf(v0,0.f); v1 = fmaxf(v1,0.f); v2 = fmaxf(v2,0.f); v3 = fmaxf(v3,0.f); }
            *(float2*)&Cg[row0 * NTOT + col]       = make_float2(v0, v1);
            *(float2*)&Cg[(row0 + 8) * NTOT + col] = make_float2(v2, v3);
        }
    }
}

// ---------------- RGCN GEMM with fused LayerNorm+ReLU epilogue ----------------
// gAgg = relu(LN( Xaug @ [W0;W1;Wr] + rowAbs*rgb )) ; K = 384, N = 128
__global__ __launch_bounds__(256, 2)
void gemm_ln(const float* __restrict__ Wab, const float* __restrict__ Wr,
             const float* __restrict__ rbias,
             const float* __restrict__ lng, const float* __restrict__ lnb)
{
    extern __shared__ float sm[];
    float* As2 = sm;
    float* Bs2 = sm + 2 * ASZ;
    float* Yb  = sm + 2 * ASZ + 2 * BSZ;   // 128 x YLD pre-LN tile
    __shared__ float sMu[128], sRs[128];
    GEMM_IDS
    const size_t Rb = (size_t)blockIdx.x * 128;
    const float* Ag = gXa;

    constexpr int CH = KAUG / 16;   // 24
    issue_stage_ln(Ag, Wab, Wr, Rb, 0, As2, Bs2, tid);
    issue_stage_ln(Ag, Wab, Wr, Rb, 1, As2 + ASZ, Bs2 + BSZ, tid);
    #pragma unroll 1
    for (int ch = 0; ch < CH; ++ch) {
        if (ch + 1 < CH) asm volatile("cp.async.wait_group 1;\n");
        else             asm volatile("cp.async.wait_group 0;\n");
        __syncthreads();
        const int s = ch & 1;
        compute_chunk(As2 + s * ASZ, 20, 0, Bs2 + s * BSZ, wr, wc, g, tg, C);
        __syncthreads();
        if (ch + 2 < CH)
            issue_stage_ln(Ag, Wab, Wr, Rb, ch + 2, As2 + s * ASZ, Bs2 + s * BSZ, tid);
    }

    // stash pre-LN into Yb, bias scaled by per-row |A| row sum
    #pragma unroll
    for (int mt = 0; mt < 2; ++mt) {
        const int r0 = wr + mt * 16 + g;
        const float ra0 = gRowA[Rb + r0];
        const float ra8 = gRowA[Rb + r0 + 8];
        #pragma unroll
        for (int nt = 0; nt < 8; ++nt) {
            const int col = wc + nt * 8 + 2 * tg;
            float2 bb = *(const float2*)&rbias[col];
            *(float2*)&Yb[r0 * YLD + col]       = make_float2(C[mt][nt][0] + ra0 * bb.x,
                                                              C[mt][nt][1] + ra0 * bb.y);
            *(float2*)&Yb[(r0 + 8) * YLD + col] = make_float2(C[mt][nt][2] + ra8 * bb.x,
                                                              C[mt][nt][3] + ra8 * bb.y);
        }
    }
    __syncthreads();

    // per-row LN stats: warp owns 16 consecutive rows
    #pragma unroll 4
    for (int rr = 0; rr < 16; ++rr) {
        const int r = warp * 16 + rr;
        float x0 = Yb[r * YLD + lane],      x1 = Yb[r * YLD + lane + 32];
        float x2 = Yb[r * YLD + lane + 64], x3 = Yb[r * YLD + lane + 96];
        float s = x0 + x1 + x2 + x3;
        float q = x0*x0 + x1*x1 + x2*x2 + x3*x3;
        #pragma unroll
        for (int o = 16; o > 0; o >>= 1) {
            s += __shfl_xor_sync(0xffffffffu, s, o);
            q += __shfl_xor_sync(0xffffffffu, q, o);
        }
        if (lane == 0) {
            float mu = s * (1.f / Dd);
            float var = q * (1.f / Dd) - mu * mu;
            sMu[r] = mu; sRs[r] = rsqrtf(var + EPS);
        }
    }
    __syncthreads();

    // normalize + relu -> gAgg
    #pragma unroll
    for (int mt = 0; mt < 2; ++mt) {
        const int rl0 = wr + mt * 16 + g;
        const size_t row0 = Rb + rl0;
        #pragma unroll
        for (int nt = 0; nt < 8; ++nt) {
            const int col = wc + nt * 8 + 2 * tg;
            float2 gvv = *(const float2*)&lng[col];
            float2 bvv = *(const float2*)&lnb[col];
            float2 y0 = *(const float2*)&Yb[rl0 * YLD + col];
            float2 y1 = *(const float2*)&Yb[(rl0 + 8) * YLD + col];
            float v0 = fmaxf((y0.x - sMu[rl0])     * sRs[rl0]     * gvv.x + bvv.x, 0.f);
            float v1 = fmaxf((y0.y - sMu[rl0])     * sRs[rl0]     * gvv.y + bvv.y, 0.f);
            float v2 = fmaxf((y1.x - sMu[rl0 + 8]) * sRs[rl0 + 8] * gvv.x + bvv.x, 0.f);
            float v3 = fmaxf((y1.y - sMu[rl0 + 8]) * sRs[rl0 + 8] * gvv.y + bvv.y, 0.f);
            *(float2*)&gAgg[row0 * Dd + col]       = make_float2(v0, v1);
            *(float2*)&gAgg[(row0 + 8) * Dd + col] = make_float2(v2, v3);
        }
    }
}

// ---------------- fused two-GEMM kernel ----------------
template<int K1, bool RESID>
__global__ __launch_bounds__(256, 2)
void fused2(const float* __restrict__ Ain,
            const float* __restrict__ Wa, const float* __restrict__ ba,
            const float* __restrict__ Wb, const float* __restrict__ bb2,
            float* __restrict__ Cg)
{
    extern __shared__ float sm[];
    float* As2 = sm;
    float* Bs2 = sm + 2 * ASZ;
    float* Yb  = sm + 2 * ASZ + 2 * BSZ;
    GEMM_IDS
    const size_t Rb = (size_t)blockIdx.x * 128;

    gemm_db<K1, Dd, true>(Ain, Wa, Rb, 0, As2, Bs2, nullptr, wr, wc, g, tg, tid, C);

    #pragma unroll
    for (int mt = 0; mt < 2; ++mt) {
        const int r0 = wr + mt * 16 + g;
        #pragma unroll
        for (int nt = 0; nt < 8; ++nt) {
            const int col = wc + nt * 8 + 2 * tg;
            float2 bb = *(const float2*)&ba[col];
            *(float2*)&Yb[r0 * YLD + col]       = make_float2(fmaxf(C[mt][nt][0] + bb.x, 0.f),
                                                              fmaxf(C[mt][nt][1] + bb.y, 0.f));
            *(float2*)&Yb[(r0 + 8) * YLD + col] = make_float2(fmaxf(C[mt][nt][2] + bb.x, 0.f),
                                                              fmaxf(C[mt][nt][3] + bb.y, 0.f));
        }
    }
    __syncthreads();

    #pragma unroll
    for (int a = 0; a < 2; ++a)
        #pragma unroll
        for (int b = 0; b < 8; ++b)
            #pragma unroll
            for (int c = 0; c < 4; ++c) C[a][b][c] = 0.f;

    gemm_db<Dd, Dd, false>(nullptr, Wb, Rb, 0, As2, Bs2, Yb, wr, wc, g, tg, tid, C);

    #pragma unroll
    for (int mt = 0; mt < 2; ++mt) {
        const size_t row0 = Rb + wr + mt * 16 + g;
        #pragma unroll
        for (int nt = 0; nt < 8; ++nt) {
            const int col = wc + nt * 8 + 2 * tg;
            float2 bb = *(const float2*)&bb2[col];
            float v0 = C[mt][nt][0] + bb.x, v1 = C[mt][nt][1] + bb.y;
            float v2 = C[mt][nt][2] + bb.x, v3 = C[mt][nt][3] + bb.y;
            if (RESID) {
                float2 r0v = *(const float2*)&Cg[row0 * Dd + col];
                float2 r1v = *(const float2*)&Cg[(row0 + 8) * Dd + col];
                v0 += r0v.x; v1 += r0v.y; v2 += r1v.x; v3 += r1v.y;
            }
            *(float2*)&Cg[row0 * Dd + col]       = make_float2(v0, v1);
            *(float2*)&Cg[(row0 + 8) * Dd + col] = make_float2(v2, v3);
        }
    }
}

// ---------------- per-graph helpers ----------------
__global__ void prep_mix(const float* __restrict__ A)
{
    __shared__ float sA[100];
    __shared__ float r0[Nn], r1[Nn];
    const int b = blockIdx.x, tid = threadIdx.x;
    for (int i = tid; i < 100; i += 32) sA[i] = A[b * 100 + i];
    __syncwarp();
    if (tid < Nn) {
        int j = tid, c1 = 0;
        #pragma unroll
        for (int i = 0; i < Nn; ++i) c1 += (sA[i * Nn + j] > 0.f);
        r1[j] = 1.f / fmaxf((float)c1, 1.f);
        r0[j] = 1.f / fmaxf((float)(Nn - c1), 1.f);
    }
    __syncwarp();
    if (tid < Nn) {
        const int t = tid;
        float m0[Nn], m1[Nn];
        #pragma unroll
        for (int i = 0; i < Nn; ++i) { m0[i] = 0.f; m1[i] = 0.f; }
        #pragma unroll
        for (int j = 0; j < Nn; ++j) {
            bool pos = sA[t * Nn + j] > 0.f;
            float cf0 = pos ? 0.f : r0[j];
            float cf1 = pos ? r1[j] : 0.f;
            #pragma unroll
            for (int i = 0; i < Nn; ++i) {
                float aij = fabsf(sA[i * Nn + j]);
                m0[i] += aij * cf0;
                m1[i] += aij * cf1;
            }
        }
        float* dst = gMix + (size_t)b * 300;
        float ra = 0.f;
        #pragma unroll
        for (int i = 0; i < Nn; ++i) {
            dst[      i * Nn + t] = m0[i];
            dst[100 + i * Nn + t] = m1[i];
            dst[200 + i * Nn + t] = fabsf(sA[i * Nn + t]);
            ra += fabsf(sA[t * Nn + i]);     // row sum of |A| for row t
        }
        gRowA[b * Nn + t] = ra;
    }
}

// Xaug[(b,i), 0:128]=M0.H, [128:256]=M1.H, [256:384]=Mr.H  (col = tid)
__global__ __launch_bounds__(128)
void mixM()
{
    __shared__ float sM[300];
    const int b = blockIdx.x, tid = threadIdx.x;
    for (int i = tid; i < 300; i += 128) sM[i] = gMix[(size_t)b * 300 + i];
    __syncthreads();

    const size_t base = (size_t)b * Nn * Dd + tid;
    float h[Nn];
    #pragma unroll
    for (int s = 0; s < Nn; ++s) h[s] = gH[base + s * Dd];

    #pragma unroll
    for (int i = 0; i < Nn; ++i) {
        float a0 = 0.f, a1 = 0.f, a2 = 0.f;
        #pragma unroll
        for (int s = 0; s < Nn; ++s) {
            float hv = h[s];
            a0 += sM[      i * Nn + s] * hv;
            a1 += sM[100 + i * Nn + s] * hv;
            a2 += sM[200 + i * Nn + s] * hv;
        }
        const size_t ro = ((size_t)b * Nn + i) * KAUG;
        gXa[ro + tid]       = a0;
        gXa[ro + 128 + tid] = a1;
        gXa[ro + 256 + tid] = a2;
    }
}

__global__ __launch_bounds__(256)
void seg_sum(const int* __restrict__ home)
{
    __shared__ float hm[Nn];
    const int b = blockIdx.x, tid = threadIdx.x;
    if (tid < Nn) hm[tid] = (float)home[b * Nn + tid];
    __syncthreads();
    const size_t base = (size_t)b * Nn * PHId + tid;
    float hs = 0.f, as = 0.f;
    #pragma unroll
    for (int i = 0; i < Nn; ++i) {
        float v = gP2[base + i * PHId];
        float m = hm[i];
        hs += v * m; as += v * (1.f - m);
    }
    gS[(size_t)b * PHId + tid]        = hs;
    gS[(size_t)(Bq + b) * PHId + tid] = as;
}

__global__ void final_k(const float* __restrict__ r2w, float* __restrict__ out)
{
    const int b = blockIdx.x, lane = threadIdx.x;
    float d = 0.f;
    #pragma unroll
    for (int c = lane; c < RHOd; c += 32)
        d += (gR[(size_t)b * RHOd + c] - gR[(size_t)(Bq + b) * RHOd + c]) * r2w[c];
    #pragma unroll
    for (int o = 16; o > 0; o >>= 1) d += __shfl_down_sync(0xffffffffu, d, o);
    if (lane == 0) out[b] = 0.5f + 0.5f * tanhf(d);
}

// ---------------- host ----------------
static float* sym(const void* s) {
    void* p = nullptr;
    cudaGetSymbolAddress(&p, s);
    return (float*)p;
}

#define SMEM_FUSED ((2 * ASZ + 2 * BSZ + 128 * YLD) * 4)

extern "C" void kernel_launch(void* const* d_in, const int* in_sizes, int n_in,
                              void* d_out, int out_size)
{
    const float* A    = (const float*)d_in[0];
    const float* X    = (const float*)d_in[1];
    const int*   home = (const int*)  d_in[2];
    const float* We1  = (const float*)d_in[3];
    const float* be1  = (const float*)d_in[4];
    const float* We2  = (const float*)d_in[5];
    const float* be2  = (const float*)d_in[6];
    const float* rgw  = (const float*)d_in[7];
    const float* rgr  = (const float*)d_in[8];
    const float* rgb  = (const float*)d_in[9];
    const float* l1w  = (const float*)d_in[10];
    const float* l1b  = (const float*)d_in[11];
    const float* l2w  = (const float*)d_in[12];
    const float* l2b  = (const float*)d_in[13];
    const float* lng  = (const float*)d_in[14];
    const float* lnb  = (const float*)d_in[15];
    const float* p1w  = (const float*)d_in[16];
    const float* p1b  = (const float*)d_in[17];
    const float* p2w  = (const float*)d_in[18];
    const float* p2b  = (const float*)d_in[19];
    const float* r1w  = (const float*)d_in[20];
    const float* r1b  = (const float*)d_in[21];
    const float* r2w  = (const float*)d_in[22];

    float* pH   = sym(gH);
    float* pAgg = sym(gAgg);
    float* pP1  = sym(gP1);
    float* pP2  = sym(gP2);
    float* pS   = sym(gS);
    float* pR   = sym(gR);

    cudaFuncSetAttribute(fused2<DIN, false>, cudaFuncAttributeMaxDynamicSharedMemorySize, SMEM_FUSED);
    cudaFuncSetAttribute(fused2<Dd,  true >, cudaFuncAttributeMaxDynamicSharedMemorySize, SMEM_FUSED);
    cudaFuncSetAttribute(gemm_ln,            cudaFuncAttributeMaxDynamicSharedMemorySize, SMEM_FUSED);

    const dim3 T(256);
    const dim3 G128(BN / 128, 1);
    const dim3 G256(BN / 128, 2);
    const dim3 GRHO(2 * Bq / 128, 1);

    prep_mix<<<Bq, 32>>>(A);

    fused2<DIN, false><<<G128, T, SMEM_FUSED>>>(X, We1, be1, We2, be2, pH);

    for (int l = 0; l < Ll; ++l) {
        mixM<<<Bq, 128>>>();
        gemm_ln<<<G128, T, SMEM_FUSED>>>(rgw + (size_t)l * 2 * Dd * Dd,
                                         rgr + (size_t)l * Dd * Dd,
                                         rgb + l * Dd, lng, lnb);
        fused2<Dd, true><<<G128, T, SMEM_FUSED>>>(pAgg,
                                                  l1w + (size_t)l * Dd * Dd, l1b + l * Dd,
                                                  l2w + (size_t)l * Dd * Dd, l2b + l * Dd,
                                                  pH);
    }

    gemm_tc<Dd,   PHId, true, true><<<G256, T>>>(pH,  p1w, p1b, pP1);
    gemm_tc<PHId, PHId, true, true><<<G256, T>>>(pP1, p2w, p2b, pP2);
    seg_sum<<<Bq, 256>>>(home);
    gemm_tc<PHId, RHOd, true, true><<<GRHO, T>>>(pS, r1w, r1b, pR);
    final_k<<<Bq, 32>>>(r2w, (float*)d_out);

    (void)in_sizes; (void)n_in; (void)out_size;
}